// round 4
// baseline (speedup 1.0000x reference)
#include <cuda_runtime.h>
#include <cuda_bf16.h>

#define B 64
#define S 128
#define NQ 2000
#define C 128
#define K 64
#define DE 64
#define DC 64
#define HP 68   // padded row stride for h in smem (16B-aligned rows, conflict-free LDS.128)
#define WP 76   // padded row stride for transposed weights (conflict-free for lane=k reads)

typedef unsigned long long ull;

// -------- scratch (device globals; no allocation allowed) --------
__device__ float d_AL[NQ * 2 * K];
__device__ float d_diffQ[NQ * C];
__device__ float d_discQ[NQ];
__device__ float d_P2[B * (S - 1) * K];
__device__ float d_P3[B * (S - 1) * K];

__device__ __forceinline__ float fsig(float x) {
    return __fdividef(1.0f, 1.0f + __expf(-x));
}

__device__ __forceinline__ ull fma2(ull a, ull b, ull c) {
    ull d;
    asm("fma.rn.f32x2 %0,%1,%2,%3;" : "=l"(d) : "l"(a), "l"(b), "l"(c));
    return d;
}
__device__ __forceinline__ float f2sum(ull v) {
    float lo, hi;
    asm("mov.b64 {%0,%1},%2;" : "=f"(lo), "=f"(hi) : "l"(v));
    return lo + hi;
}

// -------- precompute kernels --------
__global__ void k_al(const float* __restrict__ Eq, const float* __restrict__ Ec,
                     const float* __restrict__ W1, const float* __restrict__ b1) {
    int q = blockIdx.x;
    int tid = threadIdx.x;
    __shared__ float eq[DE];
    if (tid < DE) eq[tid] = Eq[q * DE + tid];
    __syncthreads();
    int corr = tid >> 6;
    int k = tid & 63;
    float a = b1[k];
#pragma unroll 4
    for (int d = 0; d < DE; d++) a = fmaf(eq[d], W1[d * K + k], a);
#pragma unroll 4
    for (int d = 0; d < DC; d++) a = fmaf(Ec[corr * DC + d], W1[(DE + d) * K + k], a);
    d_AL[(q * 2 + corr) * K + k] = a;
}

__global__ void k_dq(const float* __restrict__ Eq, const float* __restrict__ Wdiff,
                     const float* __restrict__ bdiff, const float* __restrict__ Wdisc,
                     const float* __restrict__ bdisc, const float* __restrict__ qmat) {
    int q = blockIdx.x;
    int c = threadIdx.x;
    __shared__ float eq[DE];
    if (c < DE) eq[c] = Eq[q * DE + c];
    __syncthreads();
    float a = bdiff[c];
#pragma unroll 4
    for (int d = 0; d < DE; d++) a = fmaf(eq[d], Wdiff[d * C + c], a);
    d_diffQ[q * C + c] = fsig(a) * qmat[q * C + c];
    if (c == 0) {
        float dd = bdisc[0];
        for (int d = 0; d < DE; d++) dd = fmaf(eq[d], Wdisc[d], dd);
        d_discQ[q] = fsig(dd) * 5.0f;
    }
}

__global__ void k_p23(const int* __restrict__ qseq, const int* __restrict__ cseq,
                      const float* __restrict__ W2, const float* __restrict__ W3,
                      const float* __restrict__ b2, const float* __restrict__ b3) {
    int blk = blockIdx.x;
    int b = blk / (S - 1);
    int t = blk % (S - 1);
    __shared__ float lp[K], lc[K];
    int tid = threadIdx.x;
    if (tid < K) {
        int qc = qseq[b * S + t], cc = cseq[b * S + t];
        lc[tid] = d_AL[(qc * 2 + cc) * K + tid];
        if (t > 0) {
            int qp = qseq[b * S + t - 1], cp = cseq[b * S + t - 1];
            lp[tid] = d_AL[(qp * 2 + cp) * K + tid];
        } else {
            lp[tid] = 0.0f;
        }
    }
    __syncthreads();
    int which = tid >> 6;
    int k = tid & 63;
    const float* W = which ? W3 : W2;
    float a = which ? b3[k] : b2[k];
#pragma unroll 4
    for (int j = 0; j < K; j++) a = fmaf(lp[j], W[j * K + k], a);
#pragma unroll 4
    for (int j = 0; j < K; j++) a = fmaf(lc[j], W[(K + j) * K + k], a);
    float* dst = which ? d_P3 : d_P2;
    dst[blk * K + k] = a;
}

// -------- main persistent recurrence kernel: 1 CTA per batch --------
struct Smem {
    float W4tT[K * WP];      // [j][kk]  (W4 rows 0..63 transposed)
    float W4bT[K * WP];      // [k][j]   (W4 rows 64..127 transposed)
    float W2hT[K * WP];      // [k][j]   (W2 rows 128..191 transposed)
    float W3hT[K * WP];      // [k][j]   (W3 rows 128..191 transposed)
    float hs[2][C * HP];     // double-buffered h state
    float ht[2][K];          // h_tilde double buffer
    float LGs[K];
    float lgt[K];
    float qrow[3][C];        // q_matrix rows, triple buffer
    float diffr[2][C];
    float Wabs[K];
    float b4s[K];
    float discs[2];
    float red[4];
};

__global__ void __launch_bounds__(256, 1)
lpkt_main(const int* __restrict__ qseq, const float* __restrict__ qmat,
          const float* __restrict__ h0,
          const float* __restrict__ W2, const float* __restrict__ W3,
          const float* __restrict__ W4, const float* __restrict__ b4,
          const float* __restrict__ Wab, const float* __restrict__ bab,
          float* __restrict__ out) {
    extern __shared__ char raw[];
    Smem* s = (Smem*)raw;
    const int b = blockIdx.x;
    const int tid = threadIdx.x;
    const int lane = tid & 31;
    const int ct = tid & 31;
    const int kt = tid >> 5;
    const float bab0 = __ldg(bab);

    // ---- init: transpose weights into smem ----
    for (int i = tid; i < K * K; i += 256) {
        int kk = i & 63, j = i >> 6;
        s->W4tT[j * WP + kk] = W4[kk * K + j];
    }
    for (int i = tid; i < K * K; i += 256) {
        int j = i & 63, k = i >> 6;
        s->W4bT[k * WP + j] = W4[(K + j) * K + k];
        s->W2hT[k * WP + j] = W2[(128 + j) * K + k];
        s->W3hT[k * WP + j] = W3[(128 + j) * K + k];
    }
    for (int i = tid; i < C * K; i += 256) {
        int c = i >> 6, k = i & 63;
        s->hs[0][c * HP + k] = h0[i];
    }
    if (tid < K) { s->Wabs[tid] = Wab[tid]; s->b4s[tid] = b4[tid]; }
    if (tid < C) {
        int q0 = qseq[b * S + 0], q1 = qseq[b * S + 1];
        s->qrow[0][tid] = qmat[q0 * C + tid];
        s->qrow[1][tid] = qmat[q1 * C + tid];
    }
    if (tid == 0) out[b * S] = 0.0f;
    float a2pre = 0.0f, a3pre = 0.0f;
    if (tid < K) {
        a2pre = d_P2[(b * (S - 1)) * K + tid];
        a3pre = d_P3[(b * (S - 1)) * K + tid];
    }
    __syncthreads();
    // h_tilde0 = q0row @ h0
    if (tid < K) {
        float acc0 = 0.0f, acc1 = 0.0f;
        for (int c = 0; c < C; c += 2) {
            acc0 = fmaf(s->qrow[0][c], s->hs[0][c * HP + tid], acc0);
            acc1 = fmaf(s->qrow[0][c + 1], s->hs[0][(c + 1) * HP + tid], acc1);
        }
        s->ht[0][tid] = acc0 + acc1;
    }
    __syncthreads();

    for (int t = 0; t < S - 1; t++) {
        const int t3 = t % 3;
        const int t3n = (t + 1) % 3;
        const int cb = t & 1;        // current h buffer
        const int nb = cb ^ 1;       // next h buffer
        const float* __restrict__ hcur = s->hs[cb];

        // ==== PHASE A: P1 (warps 0-1) | ability for out[t] (warps 2-5) | prefetch (warps 6-7) ====
        if (tid < 64) {
            const int k = tid;
            ull A2a = 0, A2b = 0, A3a = 0, A3b = 0;
            const float* w2p = s->W2hT + k * WP;
            const float* w3p = s->W3hT + k * WP;
            const float* htp = s->ht[cb];
#pragma unroll
            for (int q = 0; q < 16; q++) {
                ulonglong2 hp = *(const ulonglong2*)(htp + 4 * q);
                ulonglong2 w2 = *(const ulonglong2*)(w2p + 4 * q);
                ulonglong2 w3 = *(const ulonglong2*)(w3p + 4 * q);
                A2a = fma2(hp.x, w2.x, A2a); A2b = fma2(hp.y, w2.y, A2b);
                A3a = fma2(hp.x, w3.x, A3a); A3b = fma2(hp.y, w3.y, A3b);
            }
            float a2 = a2pre + f2sum(A2a) + f2sum(A2b);
            float a3 = a3pre + f2sum(A3a) + f2sum(A3b);
            // (tanh(a2)+1)*0.5 == sigmoid(2*a2)
            s->LGs[k] = fsig(a3) * fsig(2.0f * a2);
        } else if (tid < 192) {
            if (t > 0) {
                const int c = tid - 64;
                const float* hrow = hcur + c * HP;
                ull Aa = 0, Ab = 0;
#pragma unroll
                for (int q = 0; q < 16; q++) {
                    ulonglong2 hv = *(const ulonglong2*)(hrow + 4 * q);
                    ulonglong2 wv = *(const ulonglong2*)(s->Wabs + 4 * q);
                    Aa = fma2(hv.x, wv.x, Aa); Ab = fma2(hv.y, wv.y, Ab);
                }
                float abl = fsig(f2sum(Aa) + f2sum(Ab) + bab0) * s->qrow[t3][c];
                float part = s->discs[t & 1] * (abl - s->diffr[t & 1][c]);
#pragma unroll
                for (int off = 16; off; off >>= 1)
                    part += __shfl_xor_sync(0xffffffffu, part, off);
                if (lane == 0) s->red[(tid >> 5) - 2] = part;
            }
        } else {
            const int i2 = tid - 192;
            int t2 = (t + 2 < S) ? (t + 2) : (S - 1);
            int q2v = qseq[b * S + t2];
            int q1v = qseq[b * S + t + 1];
            *(float2*)(s->qrow[(t + 2) % 3] + 2 * i2) =
                *(const float2*)(qmat + q2v * C + 2 * i2);
            *(float2*)(s->diffr[(t + 1) & 1] + 2 * i2) =
                *(const float2*)(d_diffQ + q1v * C + 2 * i2);
            if (i2 == 0) s->discs[(t + 1) & 1] = d_discQ[q1v];
        }
        __syncthreads();

        // ==== PHASE B: lgt (warps 0-1) | y write (thread 64) ====
        if (tid < 64) {
            const int k = tid;
            ull La = 0, Lb = 0;
            const float* wbp = s->W4bT + k * WP;
#pragma unroll
            for (int q = 0; q < 16; q++) {
                ulonglong2 lg = *(const ulonglong2*)(s->LGs + 4 * q);
                ulonglong2 w = *(const ulonglong2*)(wbp + 4 * q);
                La = fma2(lg.x, w.x, La); Lb = fma2(lg.y, w.y, Lb);
            }
            s->lgt[k] = s->b4s[k] + f2sum(La) + f2sum(Lb);
        } else if (tid == 64 && t > 0) {
            out[b * S + t] = fsig(s->red[0] + s->red[1] + s->red[2] + s->red[3]);
        }
        __syncthreads();

        // ==== PHASE C: main matmul (f32x2) + epilogue + h_tilde + h writeback ====
        float a2n = 0.0f, a3n = 0.0f;
        if (tid < 64 && t + 1 < S - 1) {   // preload next step's P2/P3 under the matmul
            a2n = d_P2[(b * (S - 1) + t + 1) * K + tid];
            a3n = d_P3[(b * (S - 1) + t + 1) * K + tid];
        }
        float LGa[8], lga[8];
        {
            float4 x0 = *(const float4*)(s->LGs + kt * 8);
            float4 x1 = *(const float4*)(s->LGs + kt * 8 + 4);
            LGa[0] = x0.x; LGa[1] = x0.y; LGa[2] = x0.z; LGa[3] = x0.w;
            LGa[4] = x1.x; LGa[5] = x1.y; LGa[6] = x1.z; LGa[7] = x1.w;
            float4 y0 = *(const float4*)(s->lgt + kt * 8);
            float4 y1 = *(const float4*)(s->lgt + kt * 8 + 4);
            lga[0] = y0.x; lga[1] = y0.y; lga[2] = y0.z; lga[3] = y0.w;
            lga[4] = y1.x; lga[5] = y1.y; lga[6] = y1.z; lga[7] = y1.w;
        }
        float qe[4], qn[4];
#pragma unroll
        for (int i = 0; i < 4; i++) {
            qe[i] = s->qrow[t3][ct + 32 * i];
            qn[i] = s->qrow[t3n][ct + 32 * i];
        }

        ull acc[4][8];
#pragma unroll
        for (int i = 0; i < 4; i++)
#pragma unroll
            for (int jj = 0; jj < 8; jj++) acc[i][jj] = 0ull;

#pragma unroll 4
        for (int q = 0; q < 16; q++) {
            ulonglong2 hv0 = *(const ulonglong2*)(hcur + (ct)*HP + 4 * q);
            ulonglong2 hv1 = *(const ulonglong2*)(hcur + (ct + 32) * HP + 4 * q);
            ulonglong2 hv2 = *(const ulonglong2*)(hcur + (ct + 64) * HP + 4 * q);
            ulonglong2 hv3 = *(const ulonglong2*)(hcur + (ct + 96) * HP + 4 * q);
#pragma unroll
            for (int jj = 0; jj < 8; jj++) {
                ulonglong2 w = *(const ulonglong2*)(s->W4tT + (kt * 8 + jj) * WP + 4 * q);
                acc[0][jj] = fma2(hv0.x, w.x, acc[0][jj]);
                acc[0][jj] = fma2(hv0.y, w.y, acc[0][jj]);
                acc[1][jj] = fma2(hv1.x, w.x, acc[1][jj]);
                acc[1][jj] = fma2(hv1.y, w.y, acc[1][jj]);
                acc[2][jj] = fma2(hv2.x, w.x, acc[2][jj]);
                acc[2][jj] = fma2(hv2.y, w.y, acc[2][jj]);
                acc[3][jj] = fma2(hv3.x, w.x, acc[3][jj]);
                acc[3][jj] = fma2(hv3.y, w.y, acc[3][jj]);
            }
        }

        float htn[8];
#pragma unroll
        for (int jj = 0; jj < 8; jj++) htn[jj] = 0.0f;
        float* __restrict__ hnew = s->hs[nb];
#pragma unroll
        for (int i = 0; i < 4; i++) {
            int c = ct + 32 * i;
            float4 ho0 = *(const float4*)(hcur + c * HP + kt * 8);
            float4 ho1 = *(const float4*)(hcur + c * HP + kt * 8 + 4);
            float ho[8] = {ho0.x, ho0.y, ho0.z, ho0.w, ho1.x, ho1.y, ho1.z, ho1.w};
            float hn[8];
#pragma unroll
            for (int jj = 0; jj < 8; jj++) {
                float a = f2sum(acc[i][jj]) + lga[jj];
                float gf = fsig(a);
                float v = fmaf(qe[i], LGa[jj], gf * ho[jj]);
                hn[jj] = v;
                htn[jj] = fmaf(qn[i], v, htn[jj]);
            }
            *(float4*)(hnew + c * HP + kt * 8) = make_float4(hn[0], hn[1], hn[2], hn[3]);
            *(float4*)(hnew + c * HP + kt * 8 + 4) = make_float4(hn[4], hn[5], hn[6], hn[7]);
        }
        // h_tilde(t+1): reduce htn over the 32 c-lanes of each warp
#pragma unroll
        for (int jj = 0; jj < 8; jj++) {
            float v = htn[jj];
#pragma unroll
            for (int off = 16; off; off >>= 1) v += __shfl_xor_sync(0xffffffffu, v, off);
            if (lane == jj) s->ht[nb][kt * 8 + jj] = v;
        }
        a2pre = a2n;
        a3pre = a3n;
        __syncthreads();
    }

    // ==== tail: ability/y for final state (index S-1); (S-1)%3==1, (S-1)&1==1 ====
    if (tid < C) {
        const int c = tid;
        const float* hrow = s->hs[(S - 1) & 1] + c * HP;
        ull Aa = 0, Ab = 0;
#pragma unroll
        for (int q = 0; q < 16; q++) {
            ulonglong2 hv = *(const ulonglong2*)(hrow + 4 * q);
            ulonglong2 wv = *(const ulonglong2*)(s->Wabs + 4 * q);
            Aa = fma2(hv.x, wv.x, Aa); Ab = fma2(hv.y, wv.y, Ab);
        }
        float abl = fsig(f2sum(Aa) + f2sum(Ab) + bab0) * s->qrow[(S - 1) % 3][c];
        float part = s->discs[1] * (abl - s->diffr[1][c]);
#pragma unroll
        for (int off = 16; off; off >>= 1)
            part += __shfl_xor_sync(0xffffffffu, part, off);
        if (lane == 0) s->red[tid >> 5] = part;
    }
    __syncthreads();
    if (tid == 0)
        out[b * S + S - 1] = fsig(s->red[0] + s->red[1] + s->red[2] + s->red[3]);
}

// -------- launch --------
extern "C" void kernel_launch(void* const* d_in, const int* in_sizes, int n_in,
                              void* d_out, int out_size) {
    const int*   qseq  = (const int*)d_in[0];
    const int*   cseq  = (const int*)d_in[1];
    const float* qmat  = (const float*)d_in[2];
    const float* Eq    = (const float*)d_in[3];
    const float* Ec    = (const float*)d_in[4];
    const float* h0    = (const float*)d_in[5];
    const float* W1    = (const float*)d_in[6];
    const float* b1    = (const float*)d_in[7];
    const float* W2    = (const float*)d_in[8];
    const float* b2    = (const float*)d_in[9];
    const float* W3    = (const float*)d_in[10];
    const float* b3    = (const float*)d_in[11];
    const float* W4    = (const float*)d_in[12];
    const float* b4    = (const float*)d_in[13];
    const float* Wab   = (const float*)d_in[14];
    const float* bab   = (const float*)d_in[15];
    const float* Wdiff = (const float*)d_in[16];
    const float* bdiff = (const float*)d_in[17];
    const float* Wdisc = (const float*)d_in[18];
    const float* bdisc = (const float*)d_in[19];
    float* out = (float*)d_out;

    k_al<<<NQ, 128>>>(Eq, Ec, W1, b1);
    k_dq<<<NQ, 128>>>(Eq, Wdiff, bdiff, Wdisc, bdisc, qmat);
    k_p23<<<B * (S - 1), 128>>>(qseq, cseq, W2, W3, b2, b3);

    cudaFuncSetAttribute(lpkt_main, cudaFuncAttributeMaxDynamicSharedMemorySize,
                         (int)sizeof(Smem));
    lpkt_main<<<B, 256, sizeof(Smem)>>>(qseq, qmat, h0, W2, W3, W4, b4, Wab, bab, out);
}

// round 7
// speedup vs baseline: 1.5120x; 1.5120x over previous
#include <cuda_runtime.h>
#include <cuda_bf16.h>

#define B 64
#define S 128
#define NQ 2000
#define C 128
#define K 64
#define DE 64
#define DC 64
#define HP 68   // padded row stride for h in smem (16B-aligned rows, conflict-free LDS.128)
#define WP 76   // padded row stride for transposed weights

typedef unsigned long long ull;

// -------- scratch (device globals; no allocation allowed) --------
__device__ float d_AL[NQ * 2 * K];
__device__ float d_diffQ[NQ * C];
__device__ float d_discQ[NQ];
__device__ float d_P2[B * (S - 1) * K];
__device__ float d_P3[B * (S - 1) * K];

__device__ __forceinline__ float fsig(float x) {
    return __fdividef(1.0f, 1.0f + __expf(-x));
}

__device__ __forceinline__ ull fma2(ull a, ull b, ull c) {
    ull d;
    asm("fma.rn.f32x2 %0,%1,%2,%3;" : "=l"(d) : "l"(a), "l"(b), "l"(c));
    return d;
}
__device__ __forceinline__ ull add2(ull a, ull b) {
    ull d;
    asm("add.rn.f32x2 %0,%1,%2;" : "=l"(d) : "l"(a), "l"(b));
    return d;
}
__device__ __forceinline__ float f2sum(ull v) {
    float lo, hi;
    asm("mov.b64 {%0,%1},%2;" : "=f"(lo), "=f"(hi) : "l"(v));
    return lo + hi;
}

// -------- precompute kernels --------
__global__ void k_al(const float* __restrict__ Eq, const float* __restrict__ Ec,
                     const float* __restrict__ W1, const float* __restrict__ b1) {
    int q = blockIdx.x;
    int tid = threadIdx.x;
    __shared__ float eq[DE];
    if (tid < DE) eq[tid] = Eq[q * DE + tid];
    __syncthreads();
    int corr = tid >> 6;
    int k = tid & 63;
    float a = b1[k];
#pragma unroll 4
    for (int d = 0; d < DE; d++) a = fmaf(eq[d], W1[d * K + k], a);
#pragma unroll 4
    for (int d = 0; d < DC; d++) a = fmaf(Ec[corr * DC + d], W1[(DE + d) * K + k], a);
    d_AL[(q * 2 + corr) * K + k] = a;
}

__global__ void k_dq(const float* __restrict__ Eq, const float* __restrict__ Wdiff,
                     const float* __restrict__ bdiff, const float* __restrict__ Wdisc,
                     const float* __restrict__ bdisc, const float* __restrict__ qmat) {
    int q = blockIdx.x;
    int c = threadIdx.x;
    __shared__ float eq[DE];
    if (c < DE) eq[c] = Eq[q * DE + c];
    __syncthreads();
    float a = bdiff[c];
#pragma unroll 4
    for (int d = 0; d < DE; d++) a = fmaf(eq[d], Wdiff[d * C + c], a);
    d_diffQ[q * C + c] = fsig(a) * qmat[q * C + c];
    if (c == 0) {
        float dd = bdisc[0];
        for (int d = 0; d < DE; d++) dd = fmaf(eq[d], Wdisc[d], dd);
        d_discQ[q] = fsig(dd) * 5.0f;
    }
}

__global__ void k_p23(const int* __restrict__ qseq, const int* __restrict__ cseq,
                      const float* __restrict__ W2, const float* __restrict__ W3,
                      const float* __restrict__ b2, const float* __restrict__ b3) {
    int blk = blockIdx.x;
    int b = blk / (S - 1);
    int t = blk % (S - 1);
    __shared__ float lp[K], lc[K];
    int tid = threadIdx.x;
    if (tid < K) {
        int qc = qseq[b * S + t], cc = cseq[b * S + t];
        lc[tid] = d_AL[(qc * 2 + cc) * K + tid];
        if (t > 0) {
            int qp = qseq[b * S + t - 1], cp = cseq[b * S + t - 1];
            lp[tid] = d_AL[(qp * 2 + cp) * K + tid];
        } else {
            lp[tid] = 0.0f;
        }
    }
    __syncthreads();
    int which = tid >> 6;
    int k = tid & 63;
    const float* W = which ? W3 : W2;
    float a = which ? b3[k] : b2[k];
#pragma unroll 4
    for (int j = 0; j < K; j++) a = fmaf(lp[j], W[j * K + k], a);
#pragma unroll 4
    for (int j = 0; j < K; j++) a = fmaf(lc[j], W[(K + j) * K + k], a);
    float* dst = which ? d_P3 : d_P2;
    dst[blk * K + k] = a;
}

// -------- main persistent recurrence kernel: 1 CTA per batch, 512 threads --------
struct Smem {
    float W4tT[K * WP];      // [j][kk]  (W4 rows 0..63 transposed)
    float W4bT[K * WP];      // [k][j]   (W4 rows 64..127 transposed)
    float W2hT[K * WP];      // [k][j]   (W2 rows 128..191 transposed)
    float W3hT[K * WP];      // [k][j]   (W3 rows 128..191 transposed)
    float hs[2][C * HP];     // double-buffered h state
    float htp[2][K];         // h_tilde partials (per c-half)
    float LGs[K];
    float lgt[K];
    float qrow[3][C];        // q_matrix rows, triple buffer
    float diffr[2][C];
    float Wabs[K];
    float b4s[K];
    float discs[2];
    float red[4];
};

__global__ void __launch_bounds__(512, 1)
lpkt_main(const int* __restrict__ qseq, const float* __restrict__ qmat,
          const float* __restrict__ h0,
          const float* __restrict__ W2, const float* __restrict__ W3,
          const float* __restrict__ W4, const float* __restrict__ b4,
          const float* __restrict__ Wab, const float* __restrict__ bab,
          float* __restrict__ out) {
    extern __shared__ char raw[];
    Smem* s = (Smem*)raw;
    const int b = blockIdx.x;
    const int tid = threadIdx.x;
    const int lane = tid & 31;
    const int wid = tid >> 5;       // 0..15
    const int kt = wid & 7;         // k-octet
    const int ch = wid >> 3;        // c-half (0/1)
    const int ct = lane;
    const int c0 = 64 * ch + ct;    // rows c0 and c0+32
    const float bab0 = __ldg(bab);

    // ---- init: transpose weights into smem ----
    for (int i = tid; i < K * K; i += 512) {
        int kk = i & 63, j = i >> 6;
        s->W4tT[j * WP + kk] = W4[kk * K + j];
    }
    for (int i = tid; i < K * K; i += 512) {
        int j = i & 63, k = i >> 6;
        s->W4bT[k * WP + j] = W4[(K + j) * K + k];
        s->W2hT[k * WP + j] = W2[(128 + j) * K + k];
        s->W3hT[k * WP + j] = W3[(128 + j) * K + k];
    }
    for (int i = tid; i < C * K; i += 512) {
        int c = i >> 6, k = i & 63;
        s->hs[0][c * HP + k] = h0[i];
    }
    if (tid < K) { s->Wabs[tid] = Wab[tid]; s->b4s[tid] = b4[tid]; }
    if (tid < C) {
        int q0 = qseq[b * S + 0], q1 = qseq[b * S + 1];
        s->qrow[0][tid] = qmat[q0 * C + tid];
        s->qrow[1][tid] = qmat[q1 * C + tid];
    }
    if (tid == 0) out[b * S] = 0.0f;
    float a2pre = 0.0f, a3pre = 0.0f;
    if (tid < K) {
        a2pre = d_P2[(b * (S - 1)) * K + tid];
        a3pre = d_P3[(b * (S - 1)) * K + tid];
    }
    __syncthreads();
    // h_tilde0 = q0row @ h0  -> htp[0], htp[1]=0
    if (tid < K) {
        float acc0 = 0.0f, acc1 = 0.0f;
        for (int c = 0; c < C; c += 2) {
            acc0 = fmaf(s->qrow[0][c], s->hs[0][c * HP + tid], acc0);
            acc1 = fmaf(s->qrow[0][c + 1], s->hs[0][(c + 1) * HP + tid], acc1);
        }
        s->htp[0][tid] = acc0 + acc1;
        s->htp[1][tid] = 0.0f;
    }
    __syncthreads();

    for (int t = 0; t < S - 1; t++) {
        const int t3 = t % 3;
        const int t3n = (t + 1) % 3;
        const int cb = t & 1;
        const int nb = cb ^ 1;
        const float* __restrict__ hcur = s->hs[cb];

        // ==== PHASE A: P1 (warps 0-1) | ability y_t (warps 2-5) | prefetch (warps 14-15) ====
        if (tid < 64) {
            const int k = tid;
            ull A2a = 0, A2b = 0, A3a = 0, A3b = 0;
            const float* w2p = s->W2hT + k * WP;
            const float* w3p = s->W3hT + k * WP;
#pragma unroll
            for (int q = 0; q < 16; q++) {
                ulonglong2 h0p = *(const ulonglong2*)(s->htp[0] + 4 * q);
                ulonglong2 h1p = *(const ulonglong2*)(s->htp[1] + 4 * q);
                ull hx = add2(h0p.x, h1p.x);
                ull hy = add2(h0p.y, h1p.y);
                ulonglong2 w2 = *(const ulonglong2*)(w2p + 4 * q);
                ulonglong2 w3 = *(const ulonglong2*)(w3p + 4 * q);
                A2a = fma2(hx, w2.x, A2a); A2b = fma2(hy, w2.y, A2b);
                A3a = fma2(hx, w3.x, A3a); A3b = fma2(hy, w3.y, A3b);
            }
            float a2 = a2pre + f2sum(A2a) + f2sum(A2b);
            float a3 = a3pre + f2sum(A3a) + f2sum(A3b);
            // (tanh(a2)+1)*0.5 == sigmoid(2*a2)
            s->LGs[k] = fsig(a3) * fsig(2.0f * a2);
        } else if (tid < 192) {
            if (t > 0) {
                const int c = tid - 64;
                const float* hrow = hcur + c * HP;
                ull Aa = 0, Ab = 0;
#pragma unroll
                for (int q = 0; q < 16; q++) {
                    ulonglong2 hv = *(const ulonglong2*)(hrow + 4 * q);
                    ulonglong2 wv = *(const ulonglong2*)(s->Wabs + 4 * q);
                    Aa = fma2(hv.x, wv.x, Aa); Ab = fma2(hv.y, wv.y, Ab);
                }
                float abl = fsig(f2sum(Aa) + f2sum(Ab) + bab0) * s->qrow[t3][c];
                float part = s->discs[t & 1] * (abl - s->diffr[t & 1][c]);
#pragma unroll
                for (int off = 16; off; off >>= 1)
                    part += __shfl_xor_sync(0xffffffffu, part, off);
                if (lane == 0) s->red[(tid >> 5) - 2] = part;
            }
        } else if (tid >= 448) {
            const int i2 = tid - 448;
            int t2 = (t + 2 < S) ? (t + 2) : (S - 1);
            int q2v = qseq[b * S + t2];
            int q1v = qseq[b * S + t + 1];
            *(float2*)(s->qrow[(t + 2) % 3] + 2 * i2) =
                *(const float2*)(qmat + q2v * C + 2 * i2);
            *(float2*)(s->diffr[(t + 1) & 1] + 2 * i2) =
                *(const float2*)(d_diffQ + q1v * C + 2 * i2);
            if (i2 == 0) s->discs[(t + 1) & 1] = d_discQ[q1v];
        }
        __syncthreads();                                   // sync1

        // ==== PHASE C: lgt (warps 0-1, hidden under matmul) + main matmul + epilogue ====
        if (tid < 64) {
            const int k = tid;
            ull La = 0, Lb = 0;
            const float* wbp = s->W4bT + k * WP;
#pragma unroll
            for (int q = 0; q < 16; q++) {
                ulonglong2 lg = *(const ulonglong2*)(s->LGs + 4 * q);
                ulonglong2 w = *(const ulonglong2*)(wbp + 4 * q);
                La = fma2(lg.x, w.x, La); Lb = fma2(lg.y, w.y, Lb);
            }
            s->lgt[k] = s->b4s[k] + f2sum(La) + f2sum(Lb);
        } else if (tid == 479 && t > 0) {
            out[b * S + t] = fsig(s->red[0] + s->red[1] + s->red[2] + s->red[3]);
        }

        float a2n = 0.0f, a3n = 0.0f;
        if (tid < 64 && t + 1 < S - 1) {   // preload next step's P2/P3 under the matmul
            a2n = d_P2[(b * (S - 1) + t + 1) * K + tid];
            a3n = d_P3[(b * (S - 1) + t + 1) * K + tid];
        }

        ull acc[2][8];
#pragma unroll
        for (int i = 0; i < 2; i++)
#pragma unroll
            for (int jj = 0; jj < 8; jj++) acc[i][jj] = 0ull;

        const float* wbase = s->W4tT + kt * 8 * WP;
#pragma unroll 4
        for (int q = 0; q < 16; q++) {
            ulonglong2 hv0 = *(const ulonglong2*)(hcur + c0 * HP + 4 * q);
            ulonglong2 hv1 = *(const ulonglong2*)(hcur + (c0 + 32) * HP + 4 * q);
#pragma unroll
            for (int jj = 0; jj < 8; jj++) {
                ulonglong2 w = *(const ulonglong2*)(wbase + jj * WP + 4 * q);
                acc[0][jj] = fma2(hv0.x, w.x, acc[0][jj]);
                acc[0][jj] = fma2(hv0.y, w.y, acc[0][jj]);
                acc[1][jj] = fma2(hv1.x, w.x, acc[1][jj]);
                acc[1][jj] = fma2(hv1.y, w.y, acc[1][jj]);
            }
        }
        __syncthreads();                                   // sync2 (lgt ready)

        float LGa[8], lga[8];
        {
            float4 x0 = *(const float4*)(s->LGs + kt * 8);
            float4 x1 = *(const float4*)(s->LGs + kt * 8 + 4);
            LGa[0] = x0.x; LGa[1] = x0.y; LGa[2] = x0.z; LGa[3] = x0.w;
            LGa[4] = x1.x; LGa[5] = x1.y; LGa[6] = x1.z; LGa[7] = x1.w;
            float4 y0 = *(const float4*)(s->lgt + kt * 8);
            float4 y1 = *(const float4*)(s->lgt + kt * 8 + 4);
            lga[0] = y0.x; lga[1] = y0.y; lga[2] = y0.z; lga[3] = y0.w;
            lga[4] = y1.x; lga[5] = y1.y; lga[6] = y1.z; lga[7] = y1.w;
        }

        float htn[8];
#pragma unroll
        for (int jj = 0; jj < 8; jj++) htn[jj] = 0.0f;
        float* __restrict__ hnew = s->hs[nb];
#pragma unroll
        for (int i = 0; i < 2; i++) {
            int c = c0 + 32 * i;
            float qev = s->qrow[t3][c];
            float qnv = s->qrow[t3n][c];
            float4 ho0 = *(const float4*)(hcur + c * HP + kt * 8);
            float4 ho1 = *(const float4*)(hcur + c * HP + kt * 8 + 4);
            float ho[8] = {ho0.x, ho0.y, ho0.z, ho0.w, ho1.x, ho1.y, ho1.z, ho1.w};
            float hn[8];
#pragma unroll
            for (int jj = 0; jj < 8; jj++) {
                float a = f2sum(acc[i][jj]) + lga[jj];
                float gf = fsig(a);
                float v = fmaf(qev, LGa[jj], gf * ho[jj]);
                hn[jj] = v;
                htn[jj] = fmaf(qnv, v, htn[jj]);
            }
            *(float4*)(hnew + c * HP + kt * 8) = make_float4(hn[0], hn[1], hn[2], hn[3]);
            *(float4*)(hnew + c * HP + kt * 8 + 4) = make_float4(hn[4], hn[5], hn[6], hn[7]);
        }
        // h_tilde(t+1) partial for this c-half: reduce over the warp's 32 lanes
#pragma unroll
        for (int jj = 0; jj < 8; jj++) {
            float v = htn[jj];
#pragma unroll
            for (int off = 16; off; off >>= 1) v += __shfl_xor_sync(0xffffffffu, v, off);
            if (lane == jj) s->htp[ch][kt * 8 + jj] = v;
        }
        a2pre = a2n;
        a3pre = a3n;
        __syncthreads();                                   // step-end
    }

    // ==== tail: ability/y for final state (index S-1) ====
    if (tid < C) {
        const int c = tid;
        const float* hrow = s->hs[(S - 1) & 1] + c * HP;
        ull Aa = 0, Ab = 0;
#pragma unroll
        for (int q = 0; q < 16; q++) {
            ulonglong2 hv = *(const ulonglong2*)(hrow + 4 * q);
            ulonglong2 wv = *(const ulonglong2*)(s->Wabs + 4 * q);
            Aa = fma2(hv.x, wv.x, Aa); Ab = fma2(hv.y, wv.y, Ab);
        }
        float abl = fsig(f2sum(Aa) + f2sum(Ab) + bab0) * s->qrow[(S - 1) % 3][c];
        float part = s->discs[1] * (abl - s->diffr[1][c]);
#pragma unroll
        for (int off = 16; off; off >>= 1)
            part += __shfl_xor_sync(0xffffffffu, part, off);
        if (lane == 0) s->red[tid >> 5] = part;
    }
    __syncthreads();
    if (tid == 0)
        out[b * S + S - 1] = fsig(s->red[0] + s->red[1] + s->red[2] + s->red[3]);
}

// -------- launch --------
extern "C" void kernel_launch(void* const* d_in, const int* in_sizes, int n_in,
                              void* d_out, int out_size) {
    const int*   qseq  = (const int*)d_in[0];
    const int*   cseq  = (const int*)d_in[1];
    const float* qmat  = (const float*)d_in[2];
    const float* Eq    = (const float*)d_in[3];
    const float* Ec    = (const float*)d_in[4];
    const float* h0    = (const float*)d_in[5];
    const float* W1    = (const float*)d_in[6];
    const float* b1    = (const float*)d_in[7];
    const float* W2    = (const float*)d_in[8];
    const float* b2    = (const float*)d_in[9];
    const float* W3    = (const float*)d_in[10];
    const float* b3    = (const float*)d_in[11];
    const float* W4    = (const float*)d_in[12];
    const float* b4    = (const float*)d_in[13];
    const float* Wab   = (const float*)d_in[14];
    const float* bab   = (const float*)d_in[15];
    const float* Wdiff = (const float*)d_in[16];
    const float* bdiff = (const float*)d_in[17];
    const float* Wdisc = (const float*)d_in[18];
    const float* bdisc = (const float*)d_in[19];
    float* out = (float*)d_out;

    k_al<<<NQ, 128>>>(Eq, Ec, W1, b1);
    k_dq<<<NQ, 128>>>(Eq, Wdiff, bdiff, Wdisc, bdisc, qmat);
    k_p23<<<B * (S - 1), 128>>>(qseq, cseq, W2, W3, b2, b3);

    cudaFuncSetAttribute(lpkt_main, cudaFuncAttributeMaxDynamicSharedMemorySize,
                         (int)sizeof(Smem));
    lpkt_main<<<B, 512, sizeof(Smem)>>>(qseq, qmat, h0, W2, W3, W4, b4, Wab, bab, out);
}

// round 8
// speedup vs baseline: 1.8734x; 1.2390x over previous
#include <cuda_runtime.h>
#include <cuda_bf16.h>
#include <cstdint>

#define B 64
#define S 128
#define NQ 2000
#define C 128
#define K 64
#define DE 64
#define DC 64
#define HP 68   // padded row stride for h rows in smem
#define WP 76   // padded row stride for transposed weights

typedef unsigned long long ull;

// -------- scratch (device globals; no allocation allowed) --------
__device__ float d_AL[NQ * 2 * K];
__device__ float d_diffQ[NQ * C];
__device__ float d_discQ[NQ];
__device__ float d_P2[B * (S - 1) * K];
__device__ float d_P3[B * (S - 1) * K];

__device__ __forceinline__ float fsig(float x) {
    return __fdividef(1.0f, 1.0f + __expf(-x));
}
__device__ __forceinline__ ull fma2(ull a, ull b, ull c) {
    ull d;
    asm("fma.rn.f32x2 %0,%1,%2,%3;" : "=l"(d) : "l"(a), "l"(b), "l"(c));
    return d;
}
__device__ __forceinline__ ull add2(ull a, ull b) {
    ull d;
    asm("add.rn.f32x2 %0,%1,%2;" : "=l"(d) : "l"(a), "l"(b));
    return d;
}
__device__ __forceinline__ float f2sum(ull v) {
    float lo, hi;
    asm("mov.b64 {%0,%1},%2;" : "=f"(lo), "=f"(hi) : "l"(v));
    return lo + hi;
}
__device__ __forceinline__ ull packf2(float lo, float hi) {
    ull v;
    asm("mov.b64 %0,{%1,%2};" : "=l"(v) : "f"(lo), "f"(hi));
    return v;
}
__device__ __forceinline__ uint32_t s2u(const void* p) {
    uint32_t a;
    asm("{ .reg .u64 t; cvta.to.shared.u64 t, %1; cvt.u32.u64 %0, t; }" : "=r"(a) : "l"(p));
    return a;
}
__device__ __forceinline__ uint32_t ctarank() {
    uint32_t r;
    asm("mov.u32 %0, %%cluster_ctarank;" : "=r"(r));
    return r;
}
__device__ __forceinline__ void mbar_init(uint32_t a, uint32_t cnt) {
    asm volatile("mbarrier.init.shared.b64 [%0], %1;" :: "r"(a), "r"(cnt) : "memory");
}
__device__ __forceinline__ void mbar_wait_acq(uint32_t a, uint32_t par) {
    asm volatile(
        "{\n\t.reg .pred P;\n\t"
        "WL_%=:\n\t"
        "mbarrier.try_wait.parity.acquire.cluster.shared::cta.b64 P, [%0], %1, 0x989680;\n\t"
        "@!P bra WL_%=;\n\t}"
        :: "r"(a), "r"(par) : "memory");
}
__device__ __forceinline__ void remote_st64(uint32_t a, uint32_t rank, ull v) {
    asm volatile(
        "{\n\t.reg .b32 r;\n\t"
        "mapa.shared::cluster.u32 r, %0, %1;\n\t"
        "st.shared::cluster.b64 [r], %2;\n\t}"
        :: "r"(a), "r"(rank), "l"(v) : "memory");
}
__device__ __forceinline__ void remote_st32(uint32_t a, uint32_t rank, float v) {
    asm volatile(
        "{\n\t.reg .b32 r;\n\t"
        "mapa.shared::cluster.u32 r, %0, %1;\n\t"
        "st.shared::cluster.b32 [r], %2;\n\t}"
        :: "r"(a), "r"(rank), "f"(v) : "memory");
}
__device__ __forceinline__ void remote_arrive(uint32_t a, uint32_t rank) {
    asm volatile(
        "{\n\t.reg .b32 r;\n\t"
        "mapa.shared::cluster.u32 r, %0, %1;\n\t"
        "mbarrier.arrive.release.cluster.shared::cluster.b64 _, [r];\n\t}"
        :: "r"(a), "r"(rank) : "memory");
}
#define CLUSTER_SYNC_() do { \
    asm volatile("barrier.cluster.arrive.aligned;" ::: "memory"); \
    asm volatile("barrier.cluster.wait.aligned;" ::: "memory"); \
} while (0)

// -------- precompute kernels --------
__global__ void k_al(const float* __restrict__ Eq, const float* __restrict__ Ec,
                     const float* __restrict__ W1, const float* __restrict__ b1) {
    int q = blockIdx.x;
    int tid = threadIdx.x;
    __shared__ float eq[DE];
    if (tid < DE) eq[tid] = Eq[q * DE + tid];
    __syncthreads();
    int corr = tid >> 6;
    int k = tid & 63;
    float a = b1[k];
#pragma unroll 4
    for (int d = 0; d < DE; d++) a = fmaf(eq[d], W1[d * K + k], a);
#pragma unroll 4
    for (int d = 0; d < DC; d++) a = fmaf(Ec[corr * DC + d], W1[(DE + d) * K + k], a);
    d_AL[(q * 2 + corr) * K + k] = a;
}

__global__ void k_dq(const float* __restrict__ Eq, const float* __restrict__ Wdiff,
                     const float* __restrict__ bdiff, const float* __restrict__ Wdisc,
                     const float* __restrict__ bdisc, const float* __restrict__ qmat) {
    int q = blockIdx.x;
    int c = threadIdx.x;
    __shared__ float eq[DE];
    if (c < DE) eq[c] = Eq[q * DE + c];
    __syncthreads();
    float a = bdiff[c];
#pragma unroll 4
    for (int d = 0; d < DE; d++) a = fmaf(eq[d], Wdiff[d * C + c], a);
    d_diffQ[q * C + c] = fsig(a) * qmat[q * C + c];
    if (c == 0) {
        float dd = bdisc[0];
        for (int d = 0; d < DE; d++) dd = fmaf(eq[d], Wdisc[d], dd);
        d_discQ[q] = fsig(dd) * 5.0f;
    }
}

__global__ void k_p23(const int* __restrict__ qseq, const int* __restrict__ cseq,
                      const float* __restrict__ W2, const float* __restrict__ W3,
                      const float* __restrict__ b2, const float* __restrict__ b3) {
    int blk = blockIdx.x;
    int b = blk / (S - 1);
    int t = blk % (S - 1);
    __shared__ float lp[K], lc[K];
    int tid = threadIdx.x;
    if (tid < K) {
        int qc = qseq[b * S + t], cc = cseq[b * S + t];
        lc[tid] = d_AL[(qc * 2 + cc) * K + tid];
        if (t > 0) {
            int qp = qseq[b * S + t - 1], cp = cseq[b * S + t - 1];
            lp[tid] = d_AL[(qp * 2 + cp) * K + tid];
        } else {
            lp[tid] = 0.0f;
        }
    }
    __syncthreads();
    int which = tid >> 6;
    int k = tid & 63;
    const float* W = which ? W3 : W2;
    float a = which ? b3[k] : b2[k];
#pragma unroll 4
    for (int j = 0; j < K; j++) a = fmaf(lp[j], W[j * K + k], a);
#pragma unroll 4
    for (int j = 0; j < K; j++) a = fmaf(lc[j], W[(K + j) * K + k], a);
    float* dst = which ? d_P3 : d_P2;
    dst[blk * K + k] = a;
}

// -------- main kernel: cluster of 2 CTAs per batch (c-split), 512 threads each --------
struct Smem {
    float W4tT[K * WP];      // [j][kk]  (W4 rows 0..63 transposed)
    float W4bT[K * WP];      // [k][j]
    float W2hT[K * WP];      // [k][j]
    float W3hT[K * WP];      // [k][j]
    float hs[2][64 * HP];    // own 64 c-rows, double buffered
    float part[2][K];        // own h_tilde partials per c-sub-half (local)
    float htpeer[2][K];      // peer's h_tilde partial (slot = step parity)
    float LGs[K];
    float lgt[K];
    float qrow[3][C];
    float diffr[2][C];
    float Wabs[K];
    float b4s[K];
    float discs[2];
    float ypeer[2];
    ull mb_ht[2];
    ull mb_y[2];
};

__global__ void __launch_bounds__(512, 1) __cluster_dims__(2, 1, 1)
lpkt_main(const int* __restrict__ qseq, const float* __restrict__ qmat,
          const float* __restrict__ h0,
          const float* __restrict__ W2, const float* __restrict__ W3,
          const float* __restrict__ W4, const float* __restrict__ b4,
          const float* __restrict__ Wab, const float* __restrict__ bab,
          float* __restrict__ out) {
    extern __shared__ char raw[];
    Smem* s = (Smem*)raw;
    const int b = blockIdx.x >> 1;
    const uint32_t rank = ctarank();
    const uint32_t peer = rank ^ 1u;
    const int tid = threadIdx.x;
    const int lane = tid & 31;
    const int wid = tid >> 5;       // 0..15
    const int kt = wid & 7;         // k-octet
    const int ch = wid >> 3;        // c-sub-half (0/1) within own 64 rows
    const int cl = 32 * ch + lane;  // local c row 0..63
    const int gc = 64 * (int)rank + cl;  // global c
    const float bab0 = __ldg(bab);

    // ---- init: weights (transposed), own h rows, first q rows, mbarriers ----
    for (int i = tid; i < K * K; i += 512) {
        int kk = i & 63, j = i >> 6;
        s->W4tT[j * WP + kk] = W4[kk * K + j];
    }
    for (int i = tid; i < K * K; i += 512) {
        int j = i & 63, k = i >> 6;
        s->W4bT[k * WP + j] = W4[(K + j) * K + k];
        s->W2hT[k * WP + j] = W2[(128 + j) * K + k];
        s->W3hT[k * WP + j] = W3[(128 + j) * K + k];
    }
    for (int i = tid; i < 64 * K; i += 512) {
        int c = i >> 6, k = i & 63;
        s->hs[0][c * HP + k] = h0[(64 * (int)rank + c) * K + k];
    }
    if (tid < K) { s->Wabs[tid] = Wab[tid]; s->b4s[tid] = b4[tid]; }
    if (tid < C) {
        int q0 = qseq[b * S + 0], q1 = qseq[b * S + 1];
        s->qrow[0][tid] = qmat[q0 * C + tid];
        s->qrow[1][tid] = qmat[q1 * C + tid];
    }
    if (tid == 0) {
        if (rank == 0) out[b * S] = 0.0f;
        mbar_init(s2u(&s->mb_ht[0]), 16);
        mbar_init(s2u(&s->mb_ht[1]), 16);
        mbar_init(s2u(&s->mb_y[0]), 1);
        mbar_init(s2u(&s->mb_y[1]), 1);
    }
    float a2pre = 0.0f, a3pre = 0.0f;
    if (tid < K) {
        a2pre = d_P2[(b * (S - 1)) * K + tid];
        a3pre = d_P3[(b * (S - 1)) * K + tid];
    }
    __syncthreads();
    // h_tilde0 partial over own 64 rows
    if (tid < K) {
        float acc0 = 0.0f, acc1 = 0.0f;
        for (int c = 0; c < 64; c += 2) {
            acc0 = fmaf(s->qrow[0][64 * rank + c], s->hs[0][c * HP + tid], acc0);
            acc1 = fmaf(s->qrow[0][64 * rank + c + 1], s->hs[0][(c + 1) * HP + tid], acc1);
        }
        s->part[0][tid] = acc0 + acc1;
        s->part[1][tid] = 0.0f;
    }
    CLUSTER_SYNC_();   // mbarriers initialized in both CTAs; part[] visible
    // initial send: h_tilde0 partial -> peer slot 0
    if (wid == 13 && lane < 16) {
        int base = lane * 4;
        float4 p0 = *(const float4*)&s->part[0][base];
        uint32_t dst = s2u(&s->htpeer[0][base]);
        remote_st64(dst, peer, packf2(p0.x, p0.y));
        remote_st64(dst + 8, peer, packf2(p0.z, p0.w));
        remote_arrive(s2u(&s->mb_ht[0]), peer);
    }

    for (int t = 0; t < S - 1; t++) {
        const int t3 = t % 3;
        const int t3n = (t + 1) % 3;
        const int cb = t & 1;
        const int nb = cb ^ 1;
        const float* __restrict__ hcur = s->hs[cb];

        // ---- side phases (concurrent with matmul below) ----
        if (tid < 64) {
            // P1: wait peer h_tilde partial, compute LG, then lgt
            mbar_wait_acq(s2u(&s->mb_ht[cb]), (uint32_t)((t >> 1) & 1));
            const int k = tid;
            ull A2a = 0, A2b = 0, A3a = 0, A3b = 0;
            const float* w2p = s->W2hT + k * WP;
            const float* w3p = s->W3hT + k * WP;
#pragma unroll
            for (int q = 0; q < 16; q++) {
                ulonglong2 p0 = *(const ulonglong2*)(s->part[0] + 4 * q);
                ulonglong2 p1 = *(const ulonglong2*)(s->part[1] + 4 * q);
                ulonglong2 pe = *(const ulonglong2*)(s->htpeer[cb] + 4 * q);
                ull hx = add2(add2(p0.x, p1.x), pe.x);
                ull hy = add2(add2(p0.y, p1.y), pe.y);
                ulonglong2 w2v = *(const ulonglong2*)(w2p + 4 * q);
                ulonglong2 w3v = *(const ulonglong2*)(w3p + 4 * q);
                A2a = fma2(hx, w2v.x, A2a); A2b = fma2(hy, w2v.y, A2b);
                A3a = fma2(hx, w3v.x, A3a); A3b = fma2(hy, w3v.y, A3b);
            }
            float a2 = a2pre + f2sum(A2a) + f2sum(A2b);
            float a3 = a3pre + f2sum(A3a) + f2sum(A3b);
            s->LGs[k] = fsig(a3) * fsig(2.0f * a2);   // (tanh+1)/2 == sigmoid(2x)
            asm volatile("bar.sync 1, 64;" ::: "memory");
            // lgt = b4 + LG @ W4b
            ull La = 0, Lb = 0;
            const float* wbp = s->W4bT + k * WP;
#pragma unroll
            for (int q = 0; q < 16; q++) {
                ulonglong2 lg = *(const ulonglong2*)(s->LGs + 4 * q);
                ulonglong2 w = *(const ulonglong2*)(wbp + 4 * q);
                La = fma2(lg.x, w.x, La); Lb = fma2(lg.y, w.y, Lb);
            }
            s->lgt[k] = s->b4s[k] + f2sum(La) + f2sum(Lb);
            if (t + 1 < S - 1) {
                a2pre = d_P2[(b * (S - 1) + t + 1) * K + tid];
                a3pre = d_P3[(b * (S - 1) + t + 1) * K + tid];
            }
        } else if (wid == 2) {
            if (t > 0) {   // y_t over own 64 rows (2 rows per lane)
                ull Aa = 0, Ab = 0, Ba = 0, Bb = 0;
                const float* r0 = hcur + lane * HP;
                const float* r1 = hcur + (lane + 32) * HP;
#pragma unroll
                for (int q = 0; q < 16; q++) {
                    ulonglong2 wv = *(const ulonglong2*)(s->Wabs + 4 * q);
                    ulonglong2 h0v = *(const ulonglong2*)(r0 + 4 * q);
                    ulonglong2 h1v = *(const ulonglong2*)(r1 + 4 * q);
                    Aa = fma2(h0v.x, wv.x, Aa); Ab = fma2(h0v.y, wv.y, Ab);
                    Ba = fma2(h1v.x, wv.x, Ba); Bb = fma2(h1v.y, wv.y, Bb);
                }
                int g0 = 64 * rank + lane, g1 = g0 + 32;
                float abl0 = fsig(f2sum(Aa) + f2sum(Ab) + bab0) * s->qrow[t3][g0];
                float abl1 = fsig(f2sum(Ba) + f2sum(Bb) + bab0) * s->qrow[t3][g1];
                float pt = s->discs[cb] *
                           ((abl0 - s->diffr[cb][g0]) + (abl1 - s->diffr[cb][g1]));
#pragma unroll
                for (int off = 16; off; off >>= 1)
                    pt += __shfl_xor_sync(0xffffffffu, pt, off);
                if (lane == 0) {
                    if (rank == 1) {
                        remote_st32(s2u(&s->ypeer[cb]), peer, pt);
                        remote_arrive(s2u(&s->mb_y[cb]), peer);
                    } else {
                        mbar_wait_acq(s2u(&s->mb_y[cb]), (uint32_t)(((t - 1) >> 1) & 1));
                        out[b * S + t] = fsig(pt + s->ypeer[cb]);
                    }
                }
            }
        } else if (wid >= 14) {   // prefetch next q rows / diff / disc
            const int i2 = tid - 448;
            int t2 = (t + 2 < S) ? (t + 2) : (S - 1);
            int q2v = qseq[b * S + t2];
            int q1v = qseq[b * S + t + 1];
            *(float2*)(s->qrow[(t + 2) % 3] + 2 * i2) =
                *(const float2*)(qmat + q2v * C + 2 * i2);
            *(float2*)(s->diffr[nb] + 2 * i2) =
                *(const float2*)(d_diffQ + q1v * C + 2 * i2);
            if (i2 == 0) s->discs[nb] = d_discQ[q1v];
        }

        // ---- main matmul: own row cl x k-octet kt (independent of side phases) ----
        ull acc[8];
#pragma unroll
        for (int jj = 0; jj < 8; jj++) acc[jj] = 0ull;
        const float* wbase = s->W4tT + kt * 8 * WP;
        const float* hrow = hcur + cl * HP;
#pragma unroll 4
        for (int q = 0; q < 16; q++) {
            ulonglong2 hv = *(const ulonglong2*)(hrow + 4 * q);
#pragma unroll
            for (int jj = 0; jj < 8; jj++) {
                ulonglong2 w = *(const ulonglong2*)(wbase + jj * WP + 4 * q);
                acc[jj] = fma2(hv.x, w.x, acc[jj]);
                acc[jj] = fma2(hv.y, w.y, acc[jj]);
            }
        }
        __syncthreads();   // #1: LGs/lgt ready, prefetch done

        // ---- epilogue ----
        float LGa[8], lga[8];
        {
            float4 x0 = *(const float4*)(s->LGs + kt * 8);
            float4 x1 = *(const float4*)(s->LGs + kt * 8 + 4);
            LGa[0] = x0.x; LGa[1] = x0.y; LGa[2] = x0.z; LGa[3] = x0.w;
            LGa[4] = x1.x; LGa[5] = x1.y; LGa[6] = x1.z; LGa[7] = x1.w;
            float4 y0 = *(const float4*)(s->lgt + kt * 8);
            float4 y1 = *(const float4*)(s->lgt + kt * 8 + 4);
            lga[0] = y0.x; lga[1] = y0.y; lga[2] = y0.z; lga[3] = y0.w;
            lga[4] = y1.x; lga[5] = y1.y; lga[6] = y1.z; lga[7] = y1.w;
        }
        float qev = s->qrow[t3][gc];
        float qnv = s->qrow[t3n][gc];
        float4 ho0 = *(const float4*)(hcur + cl * HP + kt * 8);
        float4 ho1 = *(const float4*)(hcur + cl * HP + kt * 8 + 4);
        float ho[8] = {ho0.x, ho0.y, ho0.z, ho0.w, ho1.x, ho1.y, ho1.z, ho1.w};
        float hn[8], htn[8];
#pragma unroll
        for (int jj = 0; jj < 8; jj++) {
            float a = f2sum(acc[jj]) + lga[jj];
            float gf = fsig(a);
            float v = fmaf(qev, LGa[jj], gf * ho[jj]);
            hn[jj] = v;
            htn[jj] = qnv * v;
        }
        float* __restrict__ hnew = s->hs[nb];
        *(float4*)(hnew + cl * HP + kt * 8) = make_float4(hn[0], hn[1], hn[2], hn[3]);
        *(float4*)(hnew + cl * HP + kt * 8 + 4) = make_float4(hn[4], hn[5], hn[6], hn[7]);
#pragma unroll
        for (int jj = 0; jj < 8; jj++) {
            float v = htn[jj];
#pragma unroll
            for (int off = 16; off; off >>= 1) v += __shfl_xor_sync(0xffffffffu, v, off);
            if (lane == jj) s->part[ch][kt * 8 + jj] = v;
        }
        __syncthreads();   // #2: hnew + part complete

        // ---- send h_tilde partial for step t+1 to peer (fire and forget) ----
        if (wid == 13 && lane < 16 && t < S - 2) {
            int base = lane * 4;
            float4 p0 = *(const float4*)&s->part[0][base];
            float4 p1 = *(const float4*)&s->part[1][base];
            uint32_t dst = s2u(&s->htpeer[nb][base]);
            remote_st64(dst, peer, packf2(p0.x + p1.x, p0.y + p1.y));
            remote_st64(dst + 8, peer, packf2(p0.z + p1.z, p0.w + p1.w));
            remote_arrive(s2u(&s->mb_ht[nb]), peer);
        }
    }

    // ---- tail: y for final state (t = S-1 = 127; cb=1, t3=1) ----
    if (wid == 2) {
        const float* hfin = s->hs[1];
        ull Aa = 0, Ab = 0, Ba = 0, Bb = 0;
        const float* r0 = hfin + lane * HP;
        const float* r1 = hfin + (lane + 32) * HP;
#pragma unroll
        for (int q = 0; q < 16; q++) {
            ulonglong2 wv = *(const ulonglong2*)(s->Wabs + 4 * q);
            ulonglong2 h0v = *(const ulonglong2*)(r0 + 4 * q);
            ulonglong2 h1v = *(const ulonglong2*)(r1 + 4 * q);
            Aa = fma2(h0v.x, wv.x, Aa); Ab = fma2(h0v.y, wv.y, Ab);
            Ba = fma2(h1v.x, wv.x, Ba); Bb = fma2(h1v.y, wv.y, Bb);
        }
        int g0 = 64 * rank + lane, g1 = g0 + 32;
        float abl0 = fsig(f2sum(Aa) + f2sum(Ab) + bab0) * s->qrow[(S - 1) % 3][g0];
        float abl1 = fsig(f2sum(Ba) + f2sum(Bb) + bab0) * s->qrow[(S - 1) % 3][g1];
        float pt = s->discs[1] *
                   ((abl0 - s->diffr[1][g0]) + (abl1 - s->diffr[1][g1]));
#pragma unroll
        for (int off = 16; off; off >>= 1)
            pt += __shfl_xor_sync(0xffffffffu, pt, off);
        if (lane == 0) {
            if (rank == 1) {
                remote_st32(s2u(&s->ypeer[1]), peer, pt);
                remote_arrive(s2u(&s->mb_y[1]), peer);
            } else {
                mbar_wait_acq(s2u(&s->mb_y[1]), (uint32_t)(((S - 2) >> 1) & 1));
                out[b * S + S - 1] = fsig(pt + s->ypeer[1]);
            }
        }
    }
    CLUSTER_SYNC_();   // keep smem alive for in-flight peer writes
}

// -------- launch --------
extern "C" void kernel_launch(void* const* d_in, const int* in_sizes, int n_in,
                              void* d_out, int out_size) {
    const int*   qseq  = (const int*)d_in[0];
    const int*   cseq  = (const int*)d_in[1];
    const float* qmat  = (const float*)d_in[2];
    const float* Eq    = (const float*)d_in[3];
    const float* Ec    = (const float*)d_in[4];
    const float* h0    = (const float*)d_in[5];
    const float* W1    = (const float*)d_in[6];
    const float* b1    = (const float*)d_in[7];
    const float* W2    = (const float*)d_in[8];
    const float* b2    = (const float*)d_in[9];
    const float* W3    = (const float*)d_in[10];
    const float* b3    = (const float*)d_in[11];
    const float* W4    = (const float*)d_in[12];
    const float* b4    = (const float*)d_in[13];
    const float* Wab   = (const float*)d_in[14];
    const float* bab   = (const float*)d_in[15];
    const float* Wdiff = (const float*)d_in[16];
    const float* bdiff = (const float*)d_in[17];
    const float* Wdisc = (const float*)d_in[18];
    const float* bdisc = (const float*)d_in[19];
    float* out = (float*)d_out;

    k_al<<<NQ, 128>>>(Eq, Ec, W1, b1);
    k_dq<<<NQ, 128>>>(Eq, Wdiff, bdiff, Wdisc, bdisc, qmat);
    k_p23<<<B * (S - 1), 128>>>(qseq, cseq, W2, W3, b2, b3);

    cudaFuncSetAttribute(lpkt_main, cudaFuncAttributeMaxDynamicSharedMemorySize,
                         (int)sizeof(Smem));
    lpkt_main<<<2 * B, 512, sizeof(Smem)>>>(qseq, qmat, h0, W2, W3, W4, b4, Wab, bab, out);
}

// round 9
// speedup vs baseline: 2.1818x; 1.1646x over previous
#include <cuda_runtime.h>
#include <cuda_bf16.h>
#include <cstdint>

#define B 64
#define S 128
#define NQ 2000
#define C 128
#define K 64
#define DE 64
#define DC 64
#define HP 68   // padded row stride for h rows in smem
#define WP 76   // padded row stride for transposed weights

typedef unsigned long long ull;

// -------- scratch (device globals; no allocation allowed) --------
__device__ float d_AL[NQ * 2 * K];
__device__ float d_diffQ[NQ * C];
__device__ float d_discQ[NQ];
__device__ float d_P2[B * (S - 1) * K];
__device__ float d_P3[B * (S - 1) * K];

__device__ __forceinline__ float fsig(float x) {
    return __fdividef(1.0f, 1.0f + __expf(-x));
}
__device__ __forceinline__ ull fma2(ull a, ull b, ull c) {
    ull d;
    asm("fma.rn.f32x2 %0,%1,%2,%3;" : "=l"(d) : "l"(a), "l"(b), "l"(c));
    return d;
}
__device__ __forceinline__ ull add2(ull a, ull b) {
    ull d;
    asm("add.rn.f32x2 %0,%1,%2;" : "=l"(d) : "l"(a), "l"(b));
    return d;
}
__device__ __forceinline__ float f2sum(ull v) {
    float lo, hi;
    asm("mov.b64 {%0,%1},%2;" : "=f"(lo), "=f"(hi) : "l"(v));
    return lo + hi;
}
__device__ __forceinline__ ull packf2(float lo, float hi) {
    ull v;
    asm("mov.b64 %0,{%1,%2};" : "=l"(v) : "f"(lo), "f"(hi));
    return v;
}
__device__ __forceinline__ uint32_t s2u(const void* p) {
    uint32_t a;
    asm("{ .reg .u64 t; cvta.to.shared.u64 t, %1; cvt.u32.u64 %0, t; }" : "=r"(a) : "l"(p));
    return a;
}
__device__ __forceinline__ uint32_t ctarank() {
    uint32_t r;
    asm("mov.u32 %0, %%cluster_ctarank;" : "=r"(r));
    return r;
}
__device__ __forceinline__ void mbar_init(uint32_t a, uint32_t cnt) {
    asm volatile("mbarrier.init.shared.b64 [%0], %1;" :: "r"(a), "r"(cnt) : "memory");
}
__device__ __forceinline__ void mbar_wait_acq(uint32_t a, uint32_t par) {
    asm volatile(
        "{\n\t.reg .pred P;\n\t"
        "WL_%=:\n\t"
        "mbarrier.try_wait.parity.acquire.cluster.shared::cta.b64 P, [%0], %1, 0x989680;\n\t"
        "@!P bra WL_%=;\n\t}"
        :: "r"(a), "r"(par) : "memory");
}
__device__ __forceinline__ void remote_st64(uint32_t a, uint32_t rank, ull v) {
    asm volatile(
        "{\n\t.reg .b32 r;\n\t"
        "mapa.shared::cluster.u32 r, %0, %1;\n\t"
        "st.shared::cluster.b64 [r], %2;\n\t}"
        :: "r"(a), "r"(rank), "l"(v) : "memory");
}
__device__ __forceinline__ void remote_st32(uint32_t a, uint32_t rank, float v) {
    asm volatile(
        "{\n\t.reg .b32 r;\n\t"
        "mapa.shared::cluster.u32 r, %0, %1;\n\t"
        "st.shared::cluster.b32 [r], %2;\n\t}"
        :: "r"(a), "r"(rank), "f"(v) : "memory");
}
__device__ __forceinline__ void remote_arrive(uint32_t a, uint32_t rank) {
    asm volatile(
        "{\n\t.reg .b32 r;\n\t"
        "mapa.shared::cluster.u32 r, %0, %1;\n\t"
        "mbarrier.arrive.release.cluster.shared::cluster.b64 _, [r];\n\t}"
        :: "r"(a), "r"(rank) : "memory");
}
#define CLUSTER_SYNC_() do { \
    asm volatile("barrier.cluster.arrive.aligned;" ::: "memory"); \
    asm volatile("barrier.cluster.wait.aligned;" ::: "memory"); \
} while (0)

// -------- precompute kernels --------
__global__ void k_al(const float* __restrict__ Eq, const float* __restrict__ Ec,
                     const float* __restrict__ W1, const float* __restrict__ b1) {
    int q = blockIdx.x;
    int tid = threadIdx.x;
    __shared__ float eq[DE];
    if (tid < DE) eq[tid] = Eq[q * DE + tid];
    __syncthreads();
    int corr = tid >> 6;
    int k = tid & 63;
    float a = b1[k];
#pragma unroll 4
    for (int d = 0; d < DE; d++) a = fmaf(eq[d], W1[d * K + k], a);
#pragma unroll 4
    for (int d = 0; d < DC; d++) a = fmaf(Ec[corr * DC + d], W1[(DE + d) * K + k], a);
    d_AL[(q * 2 + corr) * K + k] = a;
}

__global__ void k_dq(const float* __restrict__ Eq, const float* __restrict__ Wdiff,
                     const float* __restrict__ bdiff, const float* __restrict__ Wdisc,
                     const float* __restrict__ bdisc, const float* __restrict__ qmat) {
    int q = blockIdx.x;
    int c = threadIdx.x;
    __shared__ float eq[DE];
    if (c < DE) eq[c] = Eq[q * DE + c];
    __syncthreads();
    float a = bdiff[c];
#pragma unroll 4
    for (int d = 0; d < DE; d++) a = fmaf(eq[d], Wdiff[d * C + c], a);
    d_diffQ[q * C + c] = fsig(a) * qmat[q * C + c];
    if (c == 0) {
        float dd = bdisc[0];
        for (int d = 0; d < DE; d++) dd = fmaf(eq[d], Wdisc[d], dd);
        d_discQ[q] = fsig(dd) * 5.0f;
    }
}

__global__ void k_p23(const int* __restrict__ qseq, const int* __restrict__ cseq,
                      const float* __restrict__ W2, const float* __restrict__ W3,
                      const float* __restrict__ b2, const float* __restrict__ b3) {
    int blk = blockIdx.x;
    int b = blk / (S - 1);
    int t = blk % (S - 1);
    __shared__ float lp[K], lc[K];
    int tid = threadIdx.x;
    if (tid < K) {
        int qc = qseq[b * S + t], cc = cseq[b * S + t];
        lc[tid] = d_AL[(qc * 2 + cc) * K + tid];
        if (t > 0) {
            int qp = qseq[b * S + t - 1], cp = cseq[b * S + t - 1];
            lp[tid] = d_AL[(qp * 2 + cp) * K + tid];
        } else {
            lp[tid] = 0.0f;
        }
    }
    __syncthreads();
    int which = tid >> 6;
    int k = tid & 63;
    const float* W = which ? W3 : W2;
    float a = which ? b3[k] : b2[k];
#pragma unroll 4
    for (int j = 0; j < K; j++) a = fmaf(lp[j], W[j * K + k], a);
#pragma unroll 4
    for (int j = 0; j < K; j++) a = fmaf(lc[j], W[(K + j) * K + k], a);
    float* dst = which ? d_P3 : d_P2;
    dst[blk * K + k] = a;
}

// -------- main kernel: cluster of 2 CTAs per batch (c-split), 512 threads each --------
// Thread map in matmul: k = 32*(wid&1)+lane (W4-top column held in registers),
// rows c = 8*(wid>>1) .. +8. h rows read as warp-uniform broadcast LDS.128.
struct Smem {
    float W4bT[K * WP];      // [k][j]
    float W2hT[K * WP];      // [k][j]
    float W3hT[K * WP];      // [k][j]
    float hs[2][64 * HP];    // own 64 c-rows, double buffered
    float part[8][K];        // per-rowgroup h_tilde partials
    float htld[K];           // reduced own+peer h_tilde (for P1 dot)
    float htpeer[2][K];      // peer's h_tilde partial (slot = step parity)
    float LGs[K];
    float lgt[K];
    float qrow[3][C];
    float diffr[2][C];
    float Wabs[K];
    float b4s[K];
    float discs[2];
    float ypeer[2];
    ull mb_ht[2];
    ull mb_y[2];
};

__global__ void __launch_bounds__(512, 1) __cluster_dims__(2, 1, 1)
lpkt_main(const int* __restrict__ qseq, const float* __restrict__ qmat,
          const float* __restrict__ h0,
          const float* __restrict__ W2, const float* __restrict__ W3,
          const float* __restrict__ W4, const float* __restrict__ b4,
          const float* __restrict__ Wab, const float* __restrict__ bab,
          float* __restrict__ out) {
    extern __shared__ char raw[];
    Smem* s = (Smem*)raw;
    const int b = blockIdx.x >> 1;
    const uint32_t rank = ctarank();
    const uint32_t peer = rank ^ 1u;
    const int tid = threadIdx.x;
    const int lane = tid & 31;
    const int wid = tid >> 5;            // 0..15
    const int kk = 32 * (wid & 1) + lane;   // owned k column
    const int g = wid >> 1;              // row group, rows 8g..8g+7
    const float bab0 = __ldg(bab);

    // ---- W4 top block column -> registers (loop-invariant, reused 127 steps) ----
    ull wreg[32];
#pragma unroll
    for (int q = 0; q < 32; q++)
        wreg[q] = packf2(W4[(2 * q) * K + kk], W4[(2 * q + 1) * K + kk]);

    // ---- init: weights (transposed) for side phases, own h rows, q rows, mbarriers ----
    for (int i = tid; i < K * K; i += 512) {
        int j = i & 63, k = i >> 6;
        s->W4bT[k * WP + j] = W4[(K + j) * K + k];
        s->W2hT[k * WP + j] = W2[(128 + j) * K + k];
        s->W3hT[k * WP + j] = W3[(128 + j) * K + k];
    }
    for (int i = tid; i < 64 * K; i += 512) {
        int c = i >> 6, k = i & 63;
        s->hs[0][c * HP + k] = h0[(64 * (int)rank + c) * K + k];
    }
    if (tid < K) { s->Wabs[tid] = Wab[tid]; s->b4s[tid] = b4[tid]; }
    if (tid < C) {
        int q0 = qseq[b * S + 0], q1 = qseq[b * S + 1];
        s->qrow[0][tid] = qmat[q0 * C + tid];
        s->qrow[1][tid] = qmat[q1 * C + tid];
    }
    if (tid == 0) {
        if (rank == 0) out[b * S] = 0.0f;
        mbar_init(s2u(&s->mb_ht[0]), 16);
        mbar_init(s2u(&s->mb_ht[1]), 16);
        mbar_init(s2u(&s->mb_y[0]), 1);
        mbar_init(s2u(&s->mb_y[1]), 1);
    }
    float a2pre = 0.0f, a3pre = 0.0f;
    if (tid < K) {
        a2pre = d_P2[(b * (S - 1)) * K + tid];
        a3pre = d_P3[(b * (S - 1)) * K + tid];
    }
    __syncthreads();
    // h_tilde0 partial over own 64 rows -> part[0]; zero part[1..7]
    if (tid < K) {
        float acc0 = 0.0f, acc1 = 0.0f;
        for (int c = 0; c < 64; c += 2) {
            acc0 = fmaf(s->qrow[0][64 * rank + c], s->hs[0][c * HP + tid], acc0);
            acc1 = fmaf(s->qrow[0][64 * rank + c + 1], s->hs[0][(c + 1) * HP + tid], acc1);
        }
        s->part[0][tid] = acc0 + acc1;
#pragma unroll
        for (int gg = 1; gg < 8; gg++) s->part[gg][tid] = 0.0f;
    }
    CLUSTER_SYNC_();   // mbarriers initialized in both CTAs; part[] visible
    // initial send: h_tilde0 partial -> peer slot 0
    if (wid == 13 && lane < 16) {
        int base = lane * 4;
        float4 p = *(const float4*)&s->part[0][base];
        uint32_t dst = s2u(&s->htpeer[0][base]);
        remote_st64(dst, peer, packf2(p.x, p.y));
        remote_st64(dst + 8, peer, packf2(p.z, p.w));
        remote_arrive(s2u(&s->mb_ht[0]), peer);
    }

    for (int t = 0; t < S - 1; t++) {
        const int t3 = t % 3;
        const int t3n = (t + 1) % 3;
        const int cb = t & 1;
        const int nb = cb ^ 1;
        const float* __restrict__ hcur = s->hs[cb];

        // ---- side phases (warps 0-1: P1; warp 2: y; warps 14-15: prefetch) ----
        if (tid < 64) {
            // reduce own partials + peer partial -> htld
            mbar_wait_acq(s2u(&s->mb_ht[cb]), (uint32_t)((t >> 1) & 1));
            float hsum = s->htpeer[cb][tid];
#pragma unroll
            for (int gg = 0; gg < 8; gg++) hsum += s->part[gg][tid];
            s->htld[tid] = hsum;
            asm volatile("bar.sync 1, 64;" ::: "memory");
            const int k = tid;
            ull A2a = 0, A2b = 0, A3a = 0, A3b = 0;
            const float* w2p = s->W2hT + k * WP;
            const float* w3p = s->W3hT + k * WP;
#pragma unroll
            for (int q = 0; q < 16; q++) {
                ulonglong2 hp = *(const ulonglong2*)(s->htld + 4 * q);
                ulonglong2 w2v = *(const ulonglong2*)(w2p + 4 * q);
                ulonglong2 w3v = *(const ulonglong2*)(w3p + 4 * q);
                A2a = fma2(hp.x, w2v.x, A2a); A2b = fma2(hp.y, w2v.y, A2b);
                A3a = fma2(hp.x, w3v.x, A3a); A3b = fma2(hp.y, w3v.y, A3b);
            }
            float a2 = a2pre + f2sum(A2a) + f2sum(A2b);
            float a3 = a3pre + f2sum(A3a) + f2sum(A3b);
            s->LGs[k] = fsig(a3) * fsig(2.0f * a2);   // (tanh+1)/2 == sigmoid(2x)
            asm volatile("bar.sync 1, 64;" ::: "memory");
            // lgt = b4 + LG @ W4b
            ull La = 0, Lb = 0;
            const float* wbp = s->W4bT + k * WP;
#pragma unroll
            for (int q = 0; q < 16; q++) {
                ulonglong2 lg = *(const ulonglong2*)(s->LGs + 4 * q);
                ulonglong2 w = *(const ulonglong2*)(wbp + 4 * q);
                La = fma2(lg.x, w.x, La); Lb = fma2(lg.y, w.y, Lb);
            }
            s->lgt[k] = s->b4s[k] + f2sum(La) + f2sum(Lb);
            if (t + 1 < S - 1) {
                a2pre = d_P2[(b * (S - 1) + t + 1) * K + tid];
                a3pre = d_P3[(b * (S - 1) + t + 1) * K + tid];
            }
        } else if (wid == 2) {
            if (t > 0) {   // y_t over own 64 rows (2 rows per lane)
                ull Aa = 0, Ab = 0, Ba = 0, Bb = 0;
                const float* r0 = hcur + lane * HP;
                const float* r1 = hcur + (lane + 32) * HP;
#pragma unroll
                for (int q = 0; q < 16; q++) {
                    ulonglong2 wv = *(const ulonglong2*)(s->Wabs + 4 * q);
                    ulonglong2 h0v = *(const ulonglong2*)(r0 + 4 * q);
                    ulonglong2 h1v = *(const ulonglong2*)(r1 + 4 * q);
                    Aa = fma2(h0v.x, wv.x, Aa); Ab = fma2(h0v.y, wv.y, Ab);
                    Ba = fma2(h1v.x, wv.x, Ba); Bb = fma2(h1v.y, wv.y, Bb);
                }
                int g0 = 64 * rank + lane, g1 = g0 + 32;
                float abl0 = fsig(f2sum(Aa) + f2sum(Ab) + bab0) * s->qrow[t3][g0];
                float abl1 = fsig(f2sum(Ba) + f2sum(Bb) + bab0) * s->qrow[t3][g1];
                float pt = s->discs[cb] *
                           ((abl0 - s->diffr[cb][g0]) + (abl1 - s->diffr[cb][g1]));
#pragma unroll
                for (int off = 16; off; off >>= 1)
                    pt += __shfl_xor_sync(0xffffffffu, pt, off);
                if (lane == 0) {
                    if (rank == 1) {
                        remote_st32(s2u(&s->ypeer[cb]), peer, pt);
                        remote_arrive(s2u(&s->mb_y[cb]), peer);
                    } else {
                        mbar_wait_acq(s2u(&s->mb_y[cb]), (uint32_t)(((t - 1) >> 1) & 1));
                        out[b * S + t] = fsig(pt + s->ypeer[cb]);
                    }
                }
            }
        } else if (wid >= 14) {   // prefetch next q rows / diff / disc
            const int i2 = tid - 448;
            int t2 = (t + 2 < S) ? (t + 2) : (S - 1);
            int q2v = qseq[b * S + t2];
            int q1v = qseq[b * S + t + 1];
            *(float2*)(s->qrow[(t + 2) % 3] + 2 * i2) =
                *(const float2*)(qmat + q2v * C + 2 * i2);
            *(float2*)(s->diffr[nb] + 2 * i2) =
                *(const float2*)(d_diffQ + q1v * C + 2 * i2);
            if (i2 == 0) s->discs[nb] = d_discQ[q1v];
        }

        // ---- main matmul: weights in registers, h rows via broadcast LDS.128 ----
        ull acc[8];
#pragma unroll
        for (int r = 0; r < 8; r++) acc[r] = 0ull;
#pragma unroll
        for (int q = 0; q < 16; q++) {
#pragma unroll
            for (int r = 0; r < 8; r++) {
                const float* hr = hcur + (8 * g + r) * HP;
                ulonglong2 hv = *(const ulonglong2*)(hr + 4 * q);
                acc[r] = fma2(hv.x, wreg[2 * q], acc[r]);
                acc[r] = fma2(hv.y, wreg[2 * q + 1], acc[r]);
            }
        }
        __syncthreads();   // #1: LGs/lgt ready, part reads done, prefetch done

        // ---- epilogue: lane owns column kk for rows 8g..8g+7 ----
        float LGk = s->LGs[kk];
        float lgtk = s->lgt[kk];
        float htn = 0.0f;
        float* __restrict__ hnew = s->hs[nb];
#pragma unroll
        for (int r = 0; r < 8; r++) {
            int c = 8 * g + r;
            int gc = 64 * (int)rank + c;
            float qev = s->qrow[t3][gc];
            float qnv = s->qrow[t3n][gc];
            float ho = hcur[c * HP + kk];
            float a = f2sum(acc[r]) + lgtk;
            float gf = fsig(a);
            float v = fmaf(qev, LGk, gf * ho);
            hnew[c * HP + kk] = v;
            htn = fmaf(qnv, v, htn);
        }
        s->part[g][kk] = htn;
        __syncthreads();   // #2: hnew + part complete

        // ---- send h_tilde partial for step t+1 to peer (fire and forget) ----
        if (wid == 13 && lane < 16 && t < S - 2) {
            int base = lane * 4;
            float4 p = *(const float4*)&s->part[0][base];
#pragma unroll
            for (int gg = 1; gg < 8; gg++) {
                float4 t4 = *(const float4*)&s->part[gg][base];
                p.x += t4.x; p.y += t4.y; p.z += t4.z; p.w += t4.w;
            }
            uint32_t dst = s2u(&s->htpeer[nb][base]);
            remote_st64(dst, peer, packf2(p.x, p.y));
            remote_st64(dst + 8, peer, packf2(p.z, p.w));
            remote_arrive(s2u(&s->mb_ht[nb]), peer);
        }
    }

    // ---- tail: y for final state (t = S-1 = 127; buffer 1, t3 = 1) ----
    if (wid == 2) {
        const float* hfin = s->hs[1];
        ull Aa = 0, Ab = 0, Ba = 0, Bb = 0;
        const float* r0 = hfin + lane * HP;
        const float* r1 = hfin + (lane + 32) * HP;
#pragma unroll
        for (int q = 0; q < 16; q++) {
            ulonglong2 wv = *(const ulonglong2*)(s->Wabs + 4 * q);
            ulonglong2 h0v = *(const ulonglong2*)(r0 + 4 * q);
            ulonglong2 h1v = *(const ulonglong2*)(r1 + 4 * q);
            Aa = fma2(h0v.x, wv.x, Aa); Ab = fma2(h0v.y, wv.y, Ab);
            Ba = fma2(h1v.x, wv.x, Ba); Bb = fma2(h1v.y, wv.y, Bb);
        }
        int g0 = 64 * rank + lane, g1 = g0 + 32;
        float abl0 = fsig(f2sum(Aa) + f2sum(Ab) + bab0) * s->qrow[(S - 1) % 3][g0];
        float abl1 = fsig(f2sum(Ba) + f2sum(Bb) + bab0) * s->qrow[(S - 1) % 3][g1];
        float pt = s->discs[1] *
                   ((abl0 - s->diffr[1][g0]) + (abl1 - s->diffr[1][g1]));
#pragma unroll
        for (int off = 16; off; off >>= 1)
            pt += __shfl_xor_sync(0xffffffffu, pt, off);
        if (lane == 0) {
            if (rank == 1) {
                remote_st32(s2u(&s->ypeer[1]), peer, pt);
                remote_arrive(s2u(&s->mb_y[1]), peer);
            } else {
                mbar_wait_acq(s2u(&s->mb_y[1]), (uint32_t)(((S - 2) >> 1) & 1));
                out[b * S + S - 1] = fsig(pt + s->ypeer[1]);
            }
        }
    }
    CLUSTER_SYNC_();   // keep smem alive for in-flight peer writes
}

// -------- launch --------
extern "C" void kernel_launch(void* const* d_in, const int* in_sizes, int n_in,
                              void* d_out, int out_size) {
    const int*   qseq  = (const int*)d_in[0];
    const int*   cseq  = (const int*)d_in[1];
    const float* qmat  = (const float*)d_in[2];
    const float* Eq    = (const float*)d_in[3];
    const float* Ec    = (const float*)d_in[4];
    const float* h0    = (const float*)d_in[5];
    const float* W1    = (const float*)d_in[6];
    const float* b1    = (const float*)d_in[7];
    const float* W2    = (const float*)d_in[8];
    const float* b2    = (const float*)d_in[9];
    const float* W3    = (const float*)d_in[10];
    const float* b3    = (const float*)d_in[11];
    const float* W4    = (const float*)d_in[12];
    const float* b4    = (const float*)d_in[13];
    const float* Wab   = (const float*)d_in[14];
    const float* bab   = (const float*)d_in[15];
    const float* Wdiff = (const float*)d_in[16];
    const float* bdiff = (const float*)d_in[17];
    const float* Wdisc = (const float*)d_in[18];
    const float* bdisc = (const float*)d_in[19];
    float* out = (float*)d_out;

    k_al<<<NQ, 128>>>(Eq, Ec, W1, b1);
    k_dq<<<NQ, 128>>>(Eq, Wdiff, bdiff, Wdisc, bdisc, qmat);
    k_p23<<<B * (S - 1), 128>>>(qseq, cseq, W2, W3, b2, b3);

    cudaFuncSetAttribute(lpkt_main, cudaFuncAttributeMaxDynamicSharedMemorySize,
                         (int)sizeof(Smem));
    lpkt_main<<<2 * B, 512, sizeof(Smem)>>>(qseq, qmat, h0, W2, W3, W4, b4, Wab, bab, out);
}